// round 7
// baseline (speedup 1.0000x reference)
#include <cuda_runtime.h>
#include <cstdint>

// ---------------- problem constants ----------------
#define ROWG   64
#define IN_DIM 1024
#define OUT_D  1024
#define BATCH  512

// ---------------- tiling ----------------
#define BM 128
#define BN 128
#define BK 16
#define KT (IN_DIM / BK)   // 64 k-tiles

// ---------------- smem layout (bytes) ----------------
#define A_ROW_B 48                  // 32B fp16 data + 16B pad (odd 16B-chunk stride)
#define A_STG   (BM * A_ROW_B)      // 6144
#define B_ROW_B 272                 // 256B fp16 data + 16B pad (17 chunks, odd)
#define B_STG   (BK * B_ROW_B)      // 4352

__device__ __forceinline__ uint32_t packh(float hi, float lo) {
    uint32_t w;
    asm("cvt.rn.f16x2.f32 %0, %1, %2;" : "=r"(w) : "f"(hi), "f"(lo));
    return w;
}

#define LDSM4(R, ADDR) \
    asm volatile("ldmatrix.sync.aligned.m8n8.x4.shared.b16 {%0,%1,%2,%3}, [%4];" \
        : "=r"((R)[0]), "=r"((R)[1]), "=r"((R)[2]), "=r"((R)[3]) : "r"(ADDR))

#define LDSM4T(R, ADDR) \
    asm volatile("ldmatrix.sync.aligned.m8n8.x4.trans.shared.b16 {%0,%1,%2,%3}, [%4];" \
        : "=r"((R)[0]), "=r"((R)[1]), "=r"((R)[2]), "=r"((R)[3]) : "r"(ADDR))

#define MMA16(C, A, B0, B1) \
    asm volatile("mma.sync.aligned.m16n8k16.row.col.f32.f16.f16.f32 " \
        "{%0,%1,%2,%3}, {%4,%5,%6,%7}, {%8,%9}, {%0,%1,%2,%3};" \
        : "+f"((C)[0]), "+f"((C)[1]), "+f"((C)[2]), "+f"((C)[3]) \
        : "r"((A)[0]), "r"((A)[1]), "r"((A)[2]), "r"((A)[3]), "r"(B0), "r"(B1))

__global__ __launch_bounds__(256, 2)
void gmlp_f16(const float* __restrict__ x,
              const float* __restrict__ W,
              const float* __restrict__ bias,
              float* __restrict__ out)
{
    __shared__ __align__(16) char smA[2 * A_STG];
    __shared__ __align__(16) char smB[2 * B_STG];
    const uint32_t sbA = (uint32_t)__cvta_generic_to_shared(smA);
    const uint32_t sbB = (uint32_t)__cvta_generic_to_shared(smB);

    const int r  = blockIdx.z;
    const int n0 = blockIdx.x * BN;
    const int m0 = blockIdx.y * BM;

    const int tid  = threadIdx.x;
    const int wid  = tid >> 5;
    const int lane = tid & 31;
    const int wm   = wid & 3;           // warp m-row 0..3
    const int wn   = wid >> 2;          // warp n-col 0..1
    const int g    = lane >> 2;
    const int tg   = lane & 3;

    // ---- loader assignments ----
    // A: thread -> (row = tid&127, k-half = tid>>7), 8 floats along k
    const int arow = tid & 127;
    const int akh  = tid >> 7;
    const float* xrow = x + (size_t)(m0 + arow) * (ROWG * IN_DIM)
                          + (size_t)r * IN_DIM + akh * 8;
    const uint32_t sa_sts = sbA + arow * A_ROW_B + akh * 16;

    // B: thread -> (k-row = tid>>4, n-chunk = tid&15), 8 floats along n
    const int bkr = tid >> 4;
    const int bnc = tid & 15;
    const float* wrow = W + (size_t)r * IN_DIM * OUT_D
                          + (size_t)bkr * OUT_D + n0 + bnc * 8;
    const uint32_t sb_sts = sbB + bkr * B_ROW_B + bnc * 16;

    // ---- consumer ldmatrix addresses ----
    // A frag (m16xk16): row = lane&15 (+ wm*32, + mt*16), 16B chunk = lane>>4
    const uint32_t a_ld = sbA + (wm * 32 + (lane & 15)) * A_ROW_B + (lane >> 4) * 16;
    // B frag (trans): k-row = (lane&7) + 8*((lane>>3)&1), n-chunk = wn*8 + (lane>>4)
    const uint32_t b_ld = sbB + ((lane & 7) + ((lane >> 3) & 1) * 8) * B_ROW_B
                              + (wn * 8 + (lane >> 4)) * 16;

    float acc[2][8][4];
    #pragma unroll
    for (int mt = 0; mt < 2; mt++)
        #pragma unroll
        for (int nt = 0; nt < 8; nt++)
            #pragma unroll
            for (int i = 0; i < 4; i++)
                acc[mt][nt][i] = 0.0f;

#define LOAD_GLB(T, FA, FB) do {                                            \
    const float4* ap_ = (const float4*)(xrow + (T) * BK);                   \
    float4 v0_ = ap_[0], v1_ = ap_[1];                                      \
    (FA)[0] = v0_.x; (FA)[1] = v0_.y; (FA)[2] = v0_.z; (FA)[3] = v0_.w;     \
    (FA)[4] = v1_.x; (FA)[5] = v1_.y; (FA)[6] = v1_.z; (FA)[7] = v1_.w;     \
    const float4* bp_ = (const float4*)(wrow + (size_t)(T) * BK * OUT_D);   \
    float4 u0_ = bp_[0], u1_ = bp_[1];                                      \
    (FB)[0] = u0_.x; (FB)[1] = u0_.y; (FB)[2] = u0_.z; (FB)[3] = u0_.w;     \
    (FB)[4] = u1_.x; (FB)[5] = u1_.y; (FB)[6] = u1_.z; (FB)[7] = u1_.w;     \
} while (0)

#define STS_TILE(BUF, FA, FB) do {                                          \
    uint32_t a0_ = packh((FA)[1], (FA)[0]), a1_ = packh((FA)[3], (FA)[2]);  \
    uint32_t a2_ = packh((FA)[5], (FA)[4]), a3_ = packh((FA)[7], (FA)[6]);  \
    asm volatile("st.shared.v4.b32 [%0], {%1,%2,%3,%4};"                    \
        :: "r"(sa_sts + (BUF) * A_STG), "r"(a0_), "r"(a1_), "r"(a2_), "r"(a3_)); \
    uint32_t b0_ = packh((FB)[1], (FB)[0]), b1_ = packh((FB)[3], (FB)[2]);  \
    uint32_t b2_ = packh((FB)[5], (FB)[4]), b3_ = packh((FB)[7], (FB)[6]);  \
    asm volatile("st.shared.v4.b32 [%0], {%1,%2,%3,%4};"                    \
        :: "r"(sb_sts + (BUF) * B_STG), "r"(b0_), "r"(b1_), "r"(b2_), "r"(b3_)); \
} while (0)

#define COMPUTE(BUF) do {                                                   \
    uint32_t a0_[4], a1_[4];                                                \
    LDSM4(a0_, a_ld + (BUF) * A_STG);                                       \
    LDSM4(a1_, a_ld + (BUF) * A_STG + 16 * A_ROW_B);                        \
    _Pragma("unroll")                                                       \
    for (int p_ = 0; p_ < 4; p_++) {                                        \
        uint32_t bb_[4];                                                    \
        LDSM4T(bb_, b_ld + (BUF) * B_STG + p_ * 32);                        \
        MMA16(acc[0][2 * p_],     a0_, bb_[0], bb_[1]);                     \
        MMA16(acc[1][2 * p_],     a1_, bb_[0], bb_[1]);                     \
        MMA16(acc[0][2 * p_ + 1], a0_, bb_[2], bb_[3]);                     \
        MMA16(acc[1][2 * p_ + 1], a1_, bb_[2], bb_[3]);                     \
    }                                                                       \
} while (0)

    // ---- prologue ----
    float fa0[8], fb0[8], fa1[8], fb1[8];
    LOAD_GLB(0, fa0, fb0);
    LOAD_GLB(1, fa1, fb1);
    STS_TILE(0, fa0, fb0);
    __syncthreads();

    // ---- main loop (2 k-tiles per trip, 2-deep register prefetch) ----
    #pragma unroll 1
    for (int kt = 0; kt < KT; kt += 2) {
        if (kt + 2 < KT) LOAD_GLB(kt + 2, fa0, fb0);
        COMPUTE(0);
        STS_TILE(1, fa1, fb1);          // tile kt+1 -> buf1
        __syncthreads();

        if (kt + 3 < KT) LOAD_GLB(kt + 3, fa1, fb1);
        COMPUTE(1);
        if (kt + 2 < KT) STS_TILE(0, fa0, fb0);   // tile kt+2 -> buf0
        __syncthreads();
    }

    // ---- epilogue: add bias, store ----
    const float* bp = bias + (size_t)r * OUT_D + n0;
    #pragma unroll
    for (int mt = 0; mt < 2; mt++) {
        #pragma unroll
        for (int nt = 0; nt < 8; nt++) {
            int row0 = wm * 32 + mt * 16 + g;
            int col  = wn * 64 + nt * 8 + tg * 2;
            float b0 = bp[col];
            float b1 = bp[col + 1];
            float2 v0 = make_float2(acc[mt][nt][0] + b0, acc[mt][nt][1] + b1);
            float2 v1 = make_float2(acc[mt][nt][2] + b0, acc[mt][nt][3] + b1);
            size_t o0 = ((size_t)(m0 + row0)     * ROWG + r) * OUT_D + n0 + col;
            size_t o1 = ((size_t)(m0 + row0 + 8) * ROWG + r) * OUT_D + n0 + col;
            *reinterpret_cast<float2*>(out + o0) = v0;
            *reinterpret_cast<float2*>(out + o1) = v1;
        }
    }
}

extern "C" void kernel_launch(void* const* d_in, const int* in_sizes, int n_in,
                              void* d_out, int out_size) {
    const float* x    = (const float*)d_in[0];  // (512, 64, 1024)
    const float* W    = (const float*)d_in[1];  // (64, 1024, 1024)
    const float* bias = (const float*)d_in[2];  // (64, 1024)
    float* out = (float*)d_out;                 // (512, 64, 1024)

    dim3 grid(OUT_D / BN, BATCH / BM, ROWG);    // (8, 4, 64)
    gmlp_f16<<<grid, 256>>>(x, W, bias, out);
}

// round 8
// speedup vs baseline: 1.4371x; 1.4371x over previous
#include <cuda_runtime.h>
#include <cstdint>

// ---------------- problem constants ----------------
#define ROWG   64
#define IN_DIM 1024
#define OUT_D  1024
#define BATCH  512

// ---------------- tiling ----------------
#define BM 128
#define BN 128
#define BK 32
#define KT (IN_DIM / BK)   // 32 k-tiles

// ---------------- smem layout (bytes) ----------------
#define A_ROW_B 80                  // 64B fp16 data + 16B pad (5 chunks, odd)
#define A_STG   (BM * A_ROW_B)      // 10240
#define B_ROW_B 272                 // 256B fp16 data + 16B pad (17 chunks, odd)
#define B_STG   (BK * B_ROW_B)      // 8704
#define SMEM_TOTAL (2 * (A_STG + B_STG))  // 37888

__device__ __forceinline__ uint32_t packh(float hi, float lo) {
    uint32_t w;
    asm("cvt.rn.f16x2.f32 %0, %1, %2;" : "=r"(w) : "f"(hi), "f"(lo));
    return w;
}

#define LDSM4(R, ADDR) \
    asm volatile("ldmatrix.sync.aligned.m8n8.x4.shared.b16 {%0,%1,%2,%3}, [%4];" \
        : "=r"((R)[0]), "=r"((R)[1]), "=r"((R)[2]), "=r"((R)[3]) : "r"(ADDR))

#define LDSM4T(R, ADDR) \
    asm volatile("ldmatrix.sync.aligned.m8n8.x4.trans.shared.b16 {%0,%1,%2,%3}, [%4];" \
        : "=r"((R)[0]), "=r"((R)[1]), "=r"((R)[2]), "=r"((R)[3]) : "r"(ADDR))

#define MMA16(C, A, B0, B1) \
    asm volatile("mma.sync.aligned.m16n8k16.row.col.f32.f16.f16.f32 " \
        "{%0,%1,%2,%3}, {%4,%5,%6,%7}, {%8,%9}, {%0,%1,%2,%3};" \
        : "+f"((C)[0]), "+f"((C)[1]), "+f"((C)[2]), "+f"((C)[3]) \
        : "r"((A)[0]), "r"((A)[1]), "r"((A)[2]), "r"((A)[3]), "r"(B0), "r"(B1))

__global__ __launch_bounds__(256, 2)
void gmlp_f16k32(const float* __restrict__ x,
                 const float* __restrict__ W,
                 const float* __restrict__ bias,
                 float* __restrict__ out)
{
    extern __shared__ __align__(16) char smem[];
    const uint32_t sbA = (uint32_t)__cvta_generic_to_shared(smem);
    const uint32_t sbB = sbA + 2 * A_STG;

    const int r  = blockIdx.z;
    const int n0 = blockIdx.x * BN;
    const int m0 = blockIdx.y * BM;

    const int tid  = threadIdx.x;
    const int wid  = tid >> 5;
    const int lane = tid & 31;
    const int wm   = wid & 3;
    const int wn   = wid >> 2;
    const int g    = lane >> 2;
    const int tg   = lane & 3;

    // ---- loader assignments (all LDGs fully coalesced: 8 lanes per 128B row) ----
    // A: thread t covers floats [t*8, t*8+8) of flat tile (c=0) and +2048 (c=1)
    const int arow0 = tid >> 2;              // rows 0..63 (c=0); +64 for c=1
    const int ak0   = (tid & 3) * 8;
    const float* xA = x + (size_t)(m0 + arow0) * (ROWG * IN_DIM)
                        + (size_t)r * IN_DIM + ak0;
    const size_t A_C1 = (size_t)64 * (ROWG * IN_DIM);   // +64 batch rows
    const uint32_t saA = sbA + arow0 * A_ROW_B + ak0 * 2;

    // B: thread t covers floats [t*8, t*8+8) of flat tile (c=0) and +2048 (c=1)
    const int brow0 = tid >> 4;              // k-rows 0..15 (c=0); +16 for c=1
    const int bn0   = (tid & 15) * 8;
    const float* xB = W + (size_t)r * IN_DIM * OUT_D
                        + (size_t)brow0 * OUT_D + n0 + bn0;
    const size_t B_C1 = (size_t)16 * OUT_D;             // +16 k-rows
    const uint32_t saB = sbB + brow0 * B_ROW_B + bn0 * 2;

    // ---- consumer ldmatrix addresses ----
    const uint32_t a_ld = sbA + (wm * 32 + (lane & 15)) * A_ROW_B + (lane >> 4) * 16;
    const uint32_t b_ld = sbB + ((lane & 7) + ((lane >> 3) & 1) * 8) * B_ROW_B
                              + (wn * 8 + (lane >> 4)) * 16;

    float acc[2][8][4];
    #pragma unroll
    for (int mt = 0; mt < 2; mt++)
        #pragma unroll
        for (int nt = 0; nt < 8; nt++)
            #pragma unroll
            for (int i = 0; i < 4; i++)
                acc[mt][nt][i] = 0.0f;

    float stA[16], stB[16];

#define LOAD_GLB(T) do {                                                     \
    const float4* a0_ = (const float4*)(xA + (size_t)(T) * BK);              \
    const float4* a1_ = (const float4*)(xA + (size_t)(T) * BK + A_C1);       \
    float4 v_;                                                               \
    v_ = a0_[0]; stA[0]=v_.x; stA[1]=v_.y; stA[2]=v_.z; stA[3]=v_.w;         \
    v_ = a0_[1]; stA[4]=v_.x; stA[5]=v_.y; stA[6]=v_.z; stA[7]=v_.w;         \
    v_ = a1_[0]; stA[8]=v_.x; stA[9]=v_.y; stA[10]=v_.z; stA[11]=v_.w;       \
    v_ = a1_[1]; stA[12]=v_.x; stA[13]=v_.y; stA[14]=v_.z; stA[15]=v_.w;     \
    const float4* b0_ = (const float4*)(xB + (size_t)(T) * BK * OUT_D);      \
    const float4* b1_ = (const float4*)(xB + (size_t)(T) * BK * OUT_D + B_C1); \
    v_ = b0_[0]; stB[0]=v_.x; stB[1]=v_.y; stB[2]=v_.z; stB[3]=v_.w;         \
    v_ = b0_[1]; stB[4]=v_.x; stB[5]=v_.y; stB[6]=v_.z; stB[7]=v_.w;         \
    v_ = b1_[0]; stB[8]=v_.x; stB[9]=v_.y; stB[10]=v_.z; stB[11]=v_.w;       \
    v_ = b1_[1]; stB[12]=v_.x; stB[13]=v_.y; stB[14]=v_.z; stB[15]=v_.w;     \
} while (0)

#define STS_TILE(BUF) do {                                                   \
    asm volatile("st.shared.v4.b32 [%0], {%1,%2,%3,%4};"                     \
        :: "r"(saA + (BUF) * A_STG),                                         \
           "r"(packh(stA[1],stA[0])), "r"(packh(stA[3],stA[2])),             \
           "r"(packh(stA[5],stA[4])), "r"(packh(stA[7],stA[6])));            \
    asm volatile("st.shared.v4.b32 [%0], {%1,%2,%3,%4};"                     \
        :: "r"(saA + (BUF) * A_STG + 64 * A_ROW_B),                          \
           "r"(packh(stA[9],stA[8])), "r"(packh(stA[11],stA[10])),           \
           "r"(packh(stA[13],stA[12])), "r"(packh(stA[15],stA[14])));        \
    asm volatile("st.shared.v4.b32 [%0], {%1,%2,%3,%4};"                     \
        :: "r"(saB + (BUF) * B_STG),                                         \
           "r"(packh(stB[1],stB[0])), "r"(packh(stB[3],stB[2])),             \
           "r"(packh(stB[5],stB[4])), "r"(packh(stB[7],stB[6])));            \
    asm volatile("st.shared.v4.b32 [%0], {%1,%2,%3,%4};"                     \
        :: "r"(saB + (BUF) * B_STG + 16 * B_ROW_B),                          \
           "r"(packh(stB[9],stB[8])), "r"(packh(stB[11],stB[10])),           \
           "r"(packh(stB[13],stB[12])), "r"(packh(stB[15],stB[14])));        \
} while (0)

#define COMPUTE(BUF) do {                                                    \
    _Pragma("unroll")                                                        \
    for (int ks_ = 0; ks_ < 2; ks_++) {                                      \
        uint32_t a0_[4], a1_[4];                                             \
        LDSM4(a0_, a_ld + (BUF) * A_STG + ks_ * 32);                         \
        LDSM4(a1_, a_ld + (BUF) * A_STG + ks_ * 32 + 16 * A_ROW_B);          \
        _Pragma("unroll")                                                    \
        for (int p_ = 0; p_ < 4; p_++) {                                     \
            uint32_t bb_[4];                                                 \
            LDSM4T(bb_, b_ld + (BUF) * B_STG + ks_ * (16 * B_ROW_B) + p_ * 32); \
            MMA16(acc[0][2 * p_],     a0_, bb_[0], bb_[1]);                  \
            MMA16(acc[1][2 * p_],     a1_, bb_[0], bb_[1]);                  \
            MMA16(acc[0][2 * p_ + 1], a0_, bb_[2], bb_[3]);                  \
            MMA16(acc[1][2 * p_ + 1], a1_, bb_[2], bb_[3]);                  \
        }                                                                    \
    }                                                                        \
} while (0)

    // ---- prologue ----
    LOAD_GLB(0);
    STS_TILE(0);
    __syncthreads();

    // ---- main loop: 2-buffer ring, 1-tile register prefetch ----
    #pragma unroll 1
    for (int kt = 0; kt < KT; kt++) {
        const int buf = kt & 1;
        if (kt + 1 < KT) LOAD_GLB(kt + 1);
        COMPUTE(buf);
        if (kt + 1 < KT) STS_TILE(buf ^ 1);
        __syncthreads();
    }

    // ---- epilogue: add bias, store ----
    const float* bp = bias + (size_t)r * OUT_D + n0;
    #pragma unroll
    for (int mt = 0; mt < 2; mt++) {
        #pragma unroll
        for (int nt = 0; nt < 8; nt++) {
            int row0 = wm * 32 + mt * 16 + g;
            int col  = wn * 64 + nt * 8 + tg * 2;
            float b0 = bp[col];
            float b1 = bp[col + 1];
            float2 v0 = make_float2(acc[mt][nt][0] + b0, acc[mt][nt][1] + b1);
            float2 v1 = make_float2(acc[mt][nt][2] + b0, acc[mt][nt][3] + b1);
            size_t o0 = ((size_t)(m0 + row0)     * ROWG + r) * OUT_D + n0 + col;
            size_t o1 = ((size_t)(m0 + row0 + 8) * ROWG + r) * OUT_D + n0 + col;
            *reinterpret_cast<float2*>(out + o0) = v0;
            *reinterpret_cast<float2*>(out + o1) = v1;
        }
    }
}

extern "C" void kernel_launch(void* const* d_in, const int* in_sizes, int n_in,
                              void* d_out, int out_size) {
    const float* x    = (const float*)d_in[0];  // (512, 64, 1024)
    const float* W    = (const float*)d_in[1];  // (64, 1024, 1024)
    const float* bias = (const float*)d_in[2];  // (64, 1024)
    float* out = (float*)d_out;                 // (512, 64, 1024)

    cudaFuncSetAttribute(gmlp_f16k32,
                         cudaFuncAttributeMaxDynamicSharedMemorySize, SMEM_TOTAL);
    dim3 grid(OUT_D / BN, BATCH / BM, ROWG);    // (8, 4, 64)
    gmlp_f16k32<<<grid, 256, SMEM_TOTAL>>>(x, W, bias, out);
}

// round 9
// speedup vs baseline: 1.6808x; 1.1695x over previous
#include <cuda_runtime.h>
#include <cstdint>

// ---------------- problem constants ----------------
#define ROWG   64
#define IN_DIM 1024
#define OUT_D  1024
#define BATCH  512

// ---------------- tiling ----------------
#define BM 128
#define BN 256
#define BK 32
#define KT (IN_DIM / BK)   // 32 k-tiles

// ---------------- smem layout (bytes) ----------------
#define A_ROW_B 64                  // 32 fp16, no pad (XOR swizzle)
#define A_STG   (BM * A_ROW_B)      // 8192
#define B_ROW_B 528                 // 256 fp16 (512B) + 16B pad
#define B_STG   (BK * B_ROW_B)      // 16896
#define SMEM_TOTAL (2 * (A_STG + B_STG))  // 50176

__device__ __forceinline__ uint32_t packh(float hi, float lo) {
    uint32_t w;
    asm("cvt.rn.f16x2.f32 %0, %1, %2;" : "=r"(w) : "f"(hi), "f"(lo));
    return w;
}

#define LDSM4(R, ADDR) \
    asm volatile("ldmatrix.sync.aligned.m8n8.x4.shared.b16 {%0,%1,%2,%3}, [%4];" \
        : "=r"((R)[0]), "=r"((R)[1]), "=r"((R)[2]), "=r"((R)[3]) : "r"(ADDR))

#define LDSM4T(R, ADDR) \
    asm volatile("ldmatrix.sync.aligned.m8n8.x4.trans.shared.b16 {%0,%1,%2,%3}, [%4];" \
        : "=r"((R)[0]), "=r"((R)[1]), "=r"((R)[2]), "=r"((R)[3]) : "r"(ADDR))

#define MMA16(C, A, B0, B1) \
    asm volatile("mma.sync.aligned.m16n8k16.row.col.f32.f16.f16.f32 " \
        "{%0,%1,%2,%3}, {%4,%5,%6,%7}, {%8,%9}, {%0,%1,%2,%3};" \
        : "+f"((C)[0]), "+f"((C)[1]), "+f"((C)[2]), "+f"((C)[3]) \
        : "r"((A)[0]), "r"((A)[1]), "r"((A)[2]), "r"((A)[3]), "r"(B0), "r"(B1))

__global__ __launch_bounds__(256, 1)
void gmlp_f16w64(const float* __restrict__ x,
                 const float* __restrict__ W,
                 const float* __restrict__ bias,
                 float* __restrict__ out)
{
    extern __shared__ __align__(16) char smem[];
    const uint32_t sbA = (uint32_t)__cvta_generic_to_shared(smem);
    const uint32_t sbB = sbA + 2 * A_STG;

    const int r  = blockIdx.z;
    const int n0 = blockIdx.x * BN;
    const int m0 = blockIdx.y * BM;

    const int tid  = threadIdx.x;
    const int wid  = tid >> 5;
    const int lane = tid & 31;
    const int wm   = wid & 1;            // 2 m-warps of 64 rows
    const int wn   = wid >> 1;           // 4 n-warps of 64 cols
    const int g    = lane >> 2;
    const int tg   = lane & 3;

    // ---- loader: A (128 rows x 32 fp32), fully coalesced ----
    const int arow = tid >> 2;           // rows 0..63 (c0), +64 (c1)
    const int ak   = (tid & 3) * 8;
    const float* xA = x + (size_t)(m0 + arow) * (ROWG * IN_DIM)
                        + (size_t)r * IN_DIM + ak;
    const size_t A_C1 = (size_t)64 * (ROWG * IN_DIM);
    // swizzled STS target: chunk' = (tid&3) ^ ((row>>1)&3)
    const uint32_t saA = sbA + arow * A_ROW_B
                       + (((tid & 3) ^ ((tid >> 3) & 3)) * 16);

    // ---- loader: B (32 k-rows x 256 fp32), fully coalesced ----
    const int brow = tid >> 3;           // k-rows 0..31
    const int bcol = (tid & 7) * 8;      // 8 fp32 = one fp16 chunk
    const float* xB = W + (size_t)r * IN_DIM * OUT_D
                        + (size_t)brow * OUT_D + n0 + bcol;
    const uint32_t saB = sbB + brow * B_ROW_B + (tid & 7) * 16;

    // ---- consumer ldmatrix base addresses ----
    const int v = ((lane & 15) >> 1) & 3;          // A swizzle xor for this lane
    const int h = lane >> 4;                        // chunk half
    const uint32_t aBase = sbA + (wm * 64 + (lane & 15)) * A_ROW_B + ((h ^ v) * 16);
    const uint32_t bBase = sbB + ((lane & 7) + ((lane >> 3) & 1) * 8) * B_ROW_B
                               + (wn * 8 + h) * 16;

    float acc[4][8][4];
    #pragma unroll
    for (int mt = 0; mt < 4; mt++)
        #pragma unroll
        for (int nt = 0; nt < 8; nt++)
            #pragma unroll
            for (int i = 0; i < 4; i++)
                acc[mt][nt][i] = 0.0f;

    float stA[16], stB[32];

#define LOAD_GLB(T) do {                                                     \
    const float4* a0_ = (const float4*)(xA + (size_t)(T) * BK);              \
    const float4* a1_ = (const float4*)(xA + (size_t)(T) * BK + A_C1);       \
    float4 v_;                                                               \
    v_ = a0_[0]; stA[0]=v_.x; stA[1]=v_.y; stA[2]=v_.z; stA[3]=v_.w;         \
    v_ = a0_[1]; stA[4]=v_.x; stA[5]=v_.y; stA[6]=v_.z; stA[7]=v_.w;         \
    v_ = a1_[0]; stA[8]=v_.x; stA[9]=v_.y; stA[10]=v_.z; stA[11]=v_.w;       \
    v_ = a1_[1]; stA[12]=v_.x; stA[13]=v_.y; stA[14]=v_.z; stA[15]=v_.w;     \
    _Pragma("unroll")                                                        \
    for (int c_ = 0; c_ < 4; c_++) {                                         \
        const float4* b_ = (const float4*)(xB + (size_t)(T) * BK * OUT_D + c_ * 64); \
        float4 u0_ = b_[0], u1_ = b_[1];                                     \
        stB[c_*8+0]=u0_.x; stB[c_*8+1]=u0_.y; stB[c_*8+2]=u0_.z; stB[c_*8+3]=u0_.w; \
        stB[c_*8+4]=u1_.x; stB[c_*8+5]=u1_.y; stB[c_*8+6]=u1_.z; stB[c_*8+7]=u1_.w; \
    }                                                                        \
} while (0)

#define STS_TILE(BUF) do {                                                   \
    asm volatile("st.shared.v4.b32 [%0], {%1,%2,%3,%4};"                     \
        :: "r"(saA + (BUF) * A_STG),                                         \
           "r"(packh(stA[1],stA[0])), "r"(packh(stA[3],stA[2])),             \
           "r"(packh(stA[5],stA[4])), "r"(packh(stA[7],stA[6])));            \
    asm volatile("st.shared.v4.b32 [%0], {%1,%2,%3,%4};"                     \
        :: "r"(saA + (BUF) * A_STG + 64 * A_ROW_B),                          \
           "r"(packh(stA[9],stA[8])), "r"(packh(stA[11],stA[10])),           \
           "r"(packh(stA[13],stA[12])), "r"(packh(stA[15],stA[14])));        \
    _Pragma("unroll")                                                        \
    for (int c_ = 0; c_ < 4; c_++) {                                         \
        asm volatile("st.shared.v4.b32 [%0], {%1,%2,%3,%4};"                 \
            :: "r"(saB + (BUF) * B_STG + c_ * 128),                          \
               "r"(packh(stB[c_*8+1],stB[c_*8+0])), "r"(packh(stB[c_*8+3],stB[c_*8+2])), \
               "r"(packh(stB[c_*8+5],stB[c_*8+4])), "r"(packh(stB[c_*8+7],stB[c_*8+6]))); \
    }                                                                        \
} while (0)

#define COMPUTE(BUF) do {                                                    \
    _Pragma("unroll")                                                        \
    for (int ks_ = 0; ks_ < 2; ks_++) {                                      \
        uint32_t a_[4][4];                                                   \
        _Pragma("unroll")                                                    \
        for (int mt_ = 0; mt_ < 4; mt_++)                                    \
            LDSM4(a_[mt_], (aBase + (BUF) * A_STG + mt_ * (16 * A_ROW_B)) ^ (ks_ * 32)); \
        _Pragma("unroll")                                                    \
        for (int p_ = 0; p_ < 4; p_++) {                                     \
            uint32_t bb_[4];                                                 \
            LDSM4T(bb_, bBase + (BUF) * B_STG + ks_ * (16 * B_ROW_B) + p_ * 32); \
            _Pragma("unroll")                                                \
            for (int mt_ = 0; mt_ < 4; mt_++) {                              \
                MMA16(acc[mt_][2 * p_],     a_[mt_], bb_[0], bb_[1]);        \
                MMA16(acc[mt_][2 * p_ + 1], a_[mt_], bb_[2], bb_[3]);        \
            }                                                                \
        }                                                                    \
    }                                                                        \
} while (0)

    // ---- prologue ----
    LOAD_GLB(0);
    STS_TILE(0);
    __syncthreads();

    // ---- main loop: 2-buffer ring, 1-tile register prefetch ----
    #pragma unroll 1
    for (int kt = 0; kt < KT; kt++) {
        const int buf = kt & 1;
        if (kt + 1 < KT) LOAD_GLB(kt + 1);
        COMPUTE(buf);
        if (kt + 1 < KT) STS_TILE(buf ^ 1);
        __syncthreads();
    }

    // ---- epilogue: add bias, store ----
    const float* bp = bias + (size_t)r * OUT_D + n0;
    #pragma unroll
    for (int mt = 0; mt < 4; mt++) {
        #pragma unroll
        for (int nt = 0; nt < 8; nt++) {
            int row0 = wm * 64 + mt * 16 + g;
            int col  = wn * 64 + nt * 8 + tg * 2;
            float b0 = bp[col];
            float b1 = bp[col + 1];
            float2 v0 = make_float2(acc[mt][nt][0] + b0, acc[mt][nt][1] + b1);
            float2 v1 = make_float2(acc[mt][nt][2] + b0, acc[mt][nt][3] + b1);
            size_t o0 = ((size_t)(m0 + row0)     * ROWG + r) * OUT_D + n0 + col;
            size_t o1 = ((size_t)(m0 + row0 + 8) * ROWG + r) * OUT_D + n0 + col;
            *reinterpret_cast<float2*>(out + o0) = v0;
            *reinterpret_cast<float2*>(out + o1) = v1;
        }
    }
}

extern "C" void kernel_launch(void* const* d_in, const int* in_sizes, int n_in,
                              void* d_out, int out_size) {
    const float* x    = (const float*)d_in[0];  // (512, 64, 1024)
    const float* W    = (const float*)d_in[1];  // (64, 1024, 1024)
    const float* bias = (const float*)d_in[2];  // (64, 1024)
    float* out = (float*)d_out;                 // (512, 64, 1024)

    cudaFuncSetAttribute(gmlp_f16w64,
                         cudaFuncAttributeMaxDynamicSharedMemorySize, SMEM_TOTAL);
    dim3 grid(OUT_D / BN, BATCH / BM, ROWG);    // (4, 4, 64)
    gmlp_f16w64<<<grid, 256, SMEM_TOTAL>>>(x, W, bias, out);
}